// round 16
// baseline (speedup 1.0000x reference)
#include <cuda_runtime.h>
#include <cuda_fp16.h>
#include <cstdint>

// ============================================================================
// GraphRec UV_Aggregator — register-chained mma.sync fp16 kernel, 3 CTAs/SM.
// R16: exp folded into logit producers (one barrier fewer, 3 syncs/group),
// uvatt spread across all 4 warps, index prefetch kept.
// ============================================================================

#define TPB   128
#define NB    2
#define LHIST 50
#define VROWS 100
#define SA    136    // halves stride, 128-k weight buffers
#define SH    72     // halves stride, 64-k buffers (A0, W2, A2W)

#define NI_MAX 100000
#define NR_MAX 8

// fp16 tables in m-major chunk order: row = 32 uint32 slots (128B)
__device__ __half2 g_v2e[NI_MAX * 32];
__device__ __half2 g_r2e[NR_MAX * 32];

// ---- smem byte offsets ----
#define O_A0   0u        // 128 x SH halves : e_uv -> e_r -> o
#define O_W1   18432u    // 64 x SA halves (k 0..63 = uv part, 64..127 = r part)
#define O_A1W  35840u    // 64 x SA halves (A1_top k 0..63, A1_bot k 64..127)
#define O_W2   53248u    // 64 x SH halves
#define O_A2W  62464u    // 64 x SH halves
#define O_B1   71680u
#define O_B2   71936u
#define O_AB1  72192u
#define O_AB2  72448u
#define O_A3   72704u
#define O_UVA  72960u    // 2 x 64 fp32 : uv @ A1_bot
#define O_LG   73472u    // 128 fp32 exp(logits)
#define SMEM_BYTES 73984u

__device__ __forceinline__ void mma16(float (&d)[4], uint32_t a0, uint32_t a1,
                                      uint32_t a2, uint32_t a3, uint32_t b0, uint32_t b1) {
    asm volatile(
        "mma.sync.aligned.m16n8k16.row.col.f32.f16.f16.f32 "
        "{%0,%1,%2,%3}, {%4,%5,%6,%7}, {%8,%9}, {%0,%1,%2,%3};"
        : "+f"(d[0]), "+f"(d[1]), "+f"(d[2]), "+f"(d[3])
        : "r"(a0), "r"(a1), "r"(a2), "r"(a3), "r"(b0), "r"(b1));
}

__device__ __forceinline__ uint32_t h2(float lo, float hi) {
    __half2 h = __floats2half2_rn(lo, hi);
    return *reinterpret_cast<uint32_t*>(&h);
}

// m-major chunk storage index of logical col c (per 64-col segment)
__device__ __forceinline__ int offcol(int c) {
    int gg = (c >> 4) & 3, kr = c & 15, p = kr >> 1;
    int slot = (p & 3) * 2 + (p >> 2);
    int q = slot * 2 + (kr & 1);
    return (c & ~63) + (q >> 2) * 16 + gg * 4 + (q & 3);
}

// ---- per-launch table conversion: fp32 row-major -> fp16 m-major chunks ----
__global__ void convert_tables(const float* __restrict__ v2e,
                               const float* __restrict__ r2e,
                               int nv, int nr) {
    int idx = blockIdx.x * blockDim.x + threadIdx.x;
    int totalv = nv * 32;
    if (idx < totalv) {
        int row = idx >> 5, s = idx & 31;
        int mm = s >> 3, gg = (s >> 1) & 3, jh = s & 1;
        const float* src = v2e + row * 64 + gg * 16 + (mm + jh * 4) * 2;
        g_v2e[idx] = __floats2half2_rn(src[0], src[1]);
    } else {
        int idx2 = idx - totalv;
        if (idx2 < nr * 32) {
            int row = idx2 >> 5, s = idx2 & 31;
            int mm = s >> 3, gg = (s >> 1) & 3, jh = s & 1;
            const float* src = r2e + row * 64 + gg * 16 + (mm + jh * 4) * 2;
            g_r2e[idx2] = __floats2half2_rn(src[0], src[1]);
        }
    }
}

// smem-A GEMM (K=64): all operand loads LDS.128 (2 k-groups per load).
template <int SAs, int SBs>
__device__ __forceinline__ void gemm_fw(const __half* __restrict__ As,
                                        const __half* __restrict__ Bs,
                                        float (&d)[2][8][4],
                                        int wq, int r, int m) {
    const __half* pa = As + (wq * 32 + r) * SAs + m * 16;
    const __half* pb = Bs + r * SBs + m * 16;
#pragma unroll
    for (int g4 = 0; g4 < 2; g4++) {
        uint4 aA = *(const uint4*)(pa + g4 * 8);
        uint4 aB = *(const uint4*)(pa + 8 * SAs + g4 * 8);
        uint4 aC = *(const uint4*)(pa + 16 * SAs + g4 * 8);
        uint4 aD = *(const uint4*)(pa + 24 * SAs + g4 * 8);
#pragma unroll
        for (int nt = 0; nt < 8; nt++) {
            uint4 bv = *(const uint4*)(pb + nt * 8 * SBs + g4 * 8);
            mma16(d[0][nt], aA.x, aB.x, aA.y, aB.y, bv.x, bv.y);
            mma16(d[1][nt], aC.x, aD.x, aC.y, aD.y, bv.x, bv.y);
            mma16(d[0][nt], aA.z, aB.z, aA.w, aB.w, bv.z, bv.w);
            mma16(d[1][nt], aC.z, aD.z, aC.w, aD.w, bv.z, bv.w);
        }
    }
}

// register-A GEMM (K=64): B loads LDS.128 (2 k-groups per load).
template <int SBs>
__device__ __forceinline__ void gemm_regA(const __half* __restrict__ Bs,
                                          const uint32_t (&a)[2][4][4],
                                          float (&d)[2][8][4], int r, int m) {
    const __half* pb = Bs + r * SBs + m * 16;
#pragma unroll
    for (int g4 = 0; g4 < 2; g4++) {
        const int kg = 2 * g4;
#pragma unroll
        for (int nt = 0; nt < 8; nt++) {
            uint4 bv = *(const uint4*)(pb + nt * 8 * SBs + g4 * 8);
            mma16(d[0][nt], a[0][kg][0], a[0][kg][1], a[0][kg][2], a[0][kg][3], bv.x, bv.y);
            mma16(d[1][nt], a[1][kg][0], a[1][kg][1], a[1][kg][2], a[1][kg][3], bv.x, bv.y);
            mma16(d[0][nt], a[0][kg+1][0], a[0][kg+1][1], a[0][kg+1][2], a[0][kg+1][3], bv.z, bv.w);
            mma16(d[1][nt], a[1][kg+1][0], a[1][kg+1][1], a[1][kg+1][2], a[1][kg+1][3], bv.z, bv.w);
        }
    }
}

// init accumulators with per-column bias (replaces zeroing)
__device__ __forceinline__ void bias_init(float (&d)[2][8][4],
                                          const float* __restrict__ bias, int m) {
#pragma unroll
    for (int kg = 0; kg < 4; kg++) {
        float2 bA = *(const float2*)(bias + kg * 16 + 2 * m);
        float2 bB = *(const float2*)(bias + kg * 16 + 2 * m + 8);
#pragma unroll
        for (int mt = 0; mt < 2; mt++) {
            d[mt][2*kg][0] = bA.x;  d[mt][2*kg][1] = bA.y;
            d[mt][2*kg][2] = bA.x;  d[mt][2*kg][3] = bA.y;
            d[mt][2*kg+1][0] = bB.x; d[mt][2*kg+1][1] = bB.y;
            d[mt][2*kg+1][2] = bB.x; d[mt][2*kg+1][3] = bB.y;
        }
    }
}

// accum (bias pre-folded) -> next-stage A-fragments: relu + pack only.
__device__ __forceinline__ void cvt_relu(const float (&d)[2][8][4],
                                         uint32_t (&h)[2][4][4]) {
#pragma unroll
    for (int kg = 0; kg < 4; kg++)
#pragma unroll
        for (int mt = 0; mt < 2; mt++) {
            h[mt][kg][0] = h2(fmaxf(d[mt][2*kg][0], 0.f),   fmaxf(d[mt][2*kg][1], 0.f));
            h[mt][kg][1] = h2(fmaxf(d[mt][2*kg][2], 0.f),   fmaxf(d[mt][2*kg][3], 0.f));
            h[mt][kg][2] = h2(fmaxf(d[mt][2*kg+1][0], 0.f), fmaxf(d[mt][2*kg+1][1], 0.f));
            h[mt][kg][3] = h2(fmaxf(d[mt][2*kg+1][2], 0.f), fmaxf(d[mt][2*kg+1][3], 0.f));
        }
}

// stage-3 variant: + uvatt[node(row)] (bias ab1 pre-folded into init)
__device__ __forceinline__ void cvt_relu3(const float (&d)[2][8][4],
                                          const float* __restrict__ uva,
                                          uint32_t (&h)[2][4][4],
                                          int wq, int r, int m) {
#pragma unroll
    for (int mt = 0; mt < 2; mt++) {
        int row0 = wq * 32 + mt * 16 + r;
        const float* ua = uva + ((row0 >= LHIST) ? 64 : 0);
        const float* ub = uva + ((row0 + 8 >= LHIST) ? 64 : 0);
#pragma unroll
        for (int kg = 0; kg < 4; kg++) {
            int ca = kg * 16 + 2 * m, cb = ca + 8;
            float2 uaA = *(const float2*)(ua + ca);
            float2 uaB = *(const float2*)(ua + cb);
            float2 ubA = *(const float2*)(ub + ca);
            float2 ubB = *(const float2*)(ub + cb);
            h[mt][kg][0] = h2(fmaxf(d[mt][2*kg][0] + uaA.x, 0.f),
                              fmaxf(d[mt][2*kg][1] + uaA.y, 0.f));
            h[mt][kg][1] = h2(fmaxf(d[mt][2*kg][2] + ubA.x, 0.f),
                              fmaxf(d[mt][2*kg][3] + ubA.y, 0.f));
            h[mt][kg][2] = h2(fmaxf(d[mt][2*kg+1][0] + uaB.x, 0.f),
                              fmaxf(d[mt][2*kg+1][1] + uaB.y, 0.f));
            h[mt][kg][3] = h2(fmaxf(d[mt][2*kg+1][2] + ubB.x, 0.f),
                              fmaxf(d[mt][2*kg+1][3] + ubB.y, 0.f));
        }
    }
}

// store o fragments to A0: m-major layout -> 8 STS.128
__device__ __forceinline__ void store_o(const uint32_t (&h)[2][4][4],
                                        __half* __restrict__ dst,
                                        int wq, int r, int m) {
#pragma unroll
    for (int mt = 0; mt < 2; mt++) {
        int row0 = wq * 32 + mt * 16 + r;
        __half* p0 = dst + row0 * SH + m * 16;
        __half* p1 = dst + (row0 + 8) * SH + m * 16;
        *reinterpret_cast<uint4*>(p0) =
            make_uint4(h[mt][0][0], h[mt][0][2], h[mt][1][0], h[mt][1][2]);
        *reinterpret_cast<uint4*>(p0 + 8) =
            make_uint4(h[mt][2][0], h[mt][2][2], h[mt][3][0], h[mt][3][2]);
        *reinterpret_cast<uint4*>(p1) =
            make_uint4(h[mt][0][1], h[mt][0][3], h[mt][1][1], h[mt][1][3]);
        *reinterpret_cast<uint4*>(p1 + 8) =
            make_uint4(h[mt][2][1], h[mt][2][3], h[mt][3][1], h[mt][3][3]);
    }
}

// stage weight W[K][64] (gmem row-major) -> half dst[n][k-storage].
__device__ __forceinline__ void stage_wh(__half* __restrict__ dst, const float* __restrict__ W,
                                         int K, int strh, int tid) {
    for (int idx = tid; idx < K * 64; idx += TPB) {
        int k = idx >> 6, n = idx & 63;
        dst[n * strh + offcol(k)] = __float2half_rn(W[idx]);
    }
}

// coalesced gather: each LDG.128 covers 4 complete 128B table rows
__device__ __forceinline__ void gather_coal(uint32_t* __restrict__ a0w,
                                            const uint32_t* __restrict__ table,
                                            int idx, int wid, int lane, int wrows) {
    const int seg = lane & 7;
    const int rsub = lane >> 3;
#pragma unroll
    for (int rr = 0; rr < 8; rr++) {
        int row = rr * 4 + rsub;
        int src = __shfl_sync(0xffffffffu, idx, row);
        if (row < wrows) {
            uint4 v = reinterpret_cast<const uint4*>(table + (size_t)src * 32)[seg];
            reinterpret_cast<uint4*>(a0w + (wid * 32 + row) * (SH / 2))[seg] = v;
        }
    }
}

__global__ __launch_bounds__(TPB, 3)
void uv_agg_ra(const int* __restrict__ nodes,
               const int* __restrict__ hist_uv,
               const int* __restrict__ hist_r,
               const float* __restrict__ u2e,
               const float* __restrict__ w1, const float* __restrict__ b1,
               const float* __restrict__ w2, const float* __restrict__ b2,
               const float* __restrict__ a1w, const float* __restrict__ a1b,
               const float* __restrict__ a2w, const float* __restrict__ a2b,
               const float* __restrict__ a3w, const float* __restrict__ a3b,
               float* __restrict__ out, int ngroups) {
    extern __shared__ char smem[];
    __half* hA0  = reinterpret_cast<__half*>(smem + O_A0);
    __half* hW1  = reinterpret_cast<__half*>(smem + O_W1);
    __half* hA1W = reinterpret_cast<__half*>(smem + O_A1W);
    __half* hW2  = reinterpret_cast<__half*>(smem + O_W2);
    __half* hA2W = reinterpret_cast<__half*>(smem + O_A2W);
    float* fB1  = reinterpret_cast<float*>(smem + O_B1);
    float* fB2  = reinterpret_cast<float*>(smem + O_B2);
    float* fAB1 = reinterpret_cast<float*>(smem + O_AB1);
    float* fAB2 = reinterpret_cast<float*>(smem + O_AB2);
    float* fA3  = reinterpret_cast<float*>(smem + O_A3);
    float* fUVA = reinterpret_cast<float*>(smem + O_UVA);
    float* fLG  = reinterpret_cast<float*>(smem + O_LG);

    const int tid = threadIdx.x;
    const int wid = tid >> 5, lane = tid & 31;
    const int r = lane >> 2, m = lane & 3;

    // ---- zero A0 once (rows >= VROWS stay benign forever) ----
    for (int i = tid; i < 128 * (SH / 2); i += TPB)
        reinterpret_cast<uint32_t*>(hA0)[i] = 0u;

    // ---- stage weights + biases once per CTA ----
    stage_wh(hW1, w1, 128, SA, tid);
    stage_wh(hA1W, a1w, 128, SA, tid);
    stage_wh(hW2, w2, 64, SH, tid);
    stage_wh(hA2W, a2w, 64, SH, tid);
    if (tid < 64) {
        fB1[tid]  = b1[tid];
        fB2[tid]  = b2[tid];
        fAB1[tid] = a1b[tid];
        fAB2[tid] = a2b[tid];
        fA3[tid]  = a3w[tid];
    }
    __syncthreads();

    const int sn = tid >> 6;       // softmax: node
    const int sd = tid & 63;       // softmax: dim
    const int sdo = offcol(sd);

    const int grow = wid * 32 + lane;
    const bool gvalid = grow < VROWS;
    const int gn = (grow >= LHIST) ? 1 : 0;
    const int gl = grow - gn * LHIST;
    const int wrows = (wid < 3) ? 32 : (VROWS - 96);

    const uint32_t* gv = reinterpret_cast<const uint32_t*>(g_v2e);
    const uint32_t* gr2 = reinterpret_cast<const uint32_t*>(g_r2e);
    uint32_t* a0w = reinterpret_cast<uint32_t*>(hA0);

    // uvatt assignment: all 4 warps (warp w -> node w>>1, col (w&1)*32+lane)
    const int uvn = wid >> 1;
    const int uvc = (wid & 1) * 32 + lane;

    // first group's indices
    int g = blockIdx.x;
    int iu = 0, ir = 0;
    if (g < ngroups && gvalid) {
        int hidx = (g * NB + gn) * LHIST + gl;
        iu = hist_uv[hidx]; ir = hist_r[hidx];
    }

    for (; g < ngroups; g += gridDim.x) {
        const int b0 = g * NB;

        // ---- uvatt: 4 warps, one column each ----
        {
            const float* uvg = u2e + (size_t)nodes[b0 + uvn] * 64;
            const uint4* w4 = reinterpret_cast<const uint4*>(hA1W + uvc * SA + 64);
            float acc = 0.f;
#pragma unroll
            for (int u = 0; u < 8; u++) {
                int mch = (u >> 1) * 2;
                int kb = (u & 1) * 32;
                uint4 wv = w4[u];
                float2 q;
                q = __half22float2(*reinterpret_cast<__half2*>(&wv.x));
                acc += q.x * uvg[kb + mch] + q.y * uvg[kb + mch + 1];
                q = __half22float2(*reinterpret_cast<__half2*>(&wv.y));
                acc += q.x * uvg[kb + mch + 8] + q.y * uvg[kb + mch + 9];
                q = __half22float2(*reinterpret_cast<__half2*>(&wv.z));
                acc += q.x * uvg[kb + 16 + mch] + q.y * uvg[kb + 16 + mch + 1];
                q = __half22float2(*reinterpret_cast<__half2*>(&wv.w));
                acc += q.x * uvg[kb + 16 + mch + 8] + q.y * uvg[kb + 16 + mch + 9];
            }
            fUVA[uvn * 64 + uvc] = acc;
        }

        float d[2][8][4];
        uint32_t h[2][4][4];

        // ==== GEMM1: d init = b1; e_uv @ W1a then += e_r @ W1b ====
        gather_coal(a0w, gv, iu, wid, lane, wrows);
        __syncwarp();
        bias_init(d, fB1, m);
        gemm_fw<SH, SA>(hA0, hW1, d, wid, r, m);
        __syncwarp();
        gather_coal(a0w, gr2, ir, wid, lane, wrows);
        __syncwarp();
        gemm_fw<SH, SA>(hA0, hW1 + 64, d, wid, r, m);
        cvt_relu(d, h);

        // ==== GEMM2: o = relu(H @ W2 + b2) — A from regs ====
        bias_init(d, fB2, m);
        gemm_regA<SH>(hW2, h, d, r, m);
        cvt_relu(d, h);
        __syncwarp();
        store_o(h, hA0, wid, r, m);

        // ==== GEMM3: H2 = relu(o @ A1_top + ab1 + uvatt[n]) — A from regs ====
        bias_init(d, fAB1, m);
        gemm_regA<SA>(hA1W, h, d, r, m);
        __syncthreads();                   // S1: uvatt visible to all warps
        cvt_relu3(d, fUVA, h, wid, r, m);

        // ==== GEMM4 + full logit dot (ab2 pre-folded); exp at producer ====
        bias_init(d, fAB2, m);
        gemm_regA<SH>(hA2W, h, d, r, m);
        {
            float p0[2] = {0.f, 0.f}, p1[2] = {0.f, 0.f};
#pragma unroll
            for (int mt = 0; mt < 2; mt++)
#pragma unroll
                for (int nt = 0; nt < 8; nt++) {
                    int c0 = nt * 8 + 2 * m;
                    float w30 = fA3[c0], w31 = fA3[c0 + 1];
                    p0[mt] += fmaxf(d[mt][nt][0], 0.f) * w30
                            + fmaxf(d[mt][nt][1], 0.f) * w31;
                    p1[mt] += fmaxf(d[mt][nt][2], 0.f) * w30
                            + fmaxf(d[mt][nt][3], 0.f) * w31;
                }
#pragma unroll
            for (int off = 1; off <= 2; off <<= 1) {
#pragma unroll
                for (int mt = 0; mt < 2; mt++) {
                    p0[mt] += __shfl_xor_sync(0xffffffffu, p0[mt], off);
                    p1[mt] += __shfl_xor_sync(0xffffffffu, p1[mt], off);
                }
            }
            if (m == 0) {
#pragma unroll
                for (int mt = 0; mt < 2; mt++) {
                    int row = wid * 32 + mt * 16 + r;
                    fLG[row] = __expf(p0[mt]);        // exp once per logit
                    fLG[row + 8] = __expf(p1[mt]);
                }
            }
        }

        // ---- prefetch next group's gather indices (hidden behind softmax) ----
        int gnext = g + gridDim.x;
        int iu2 = 0, ir2 = 0;
        if (gnext < ngroups && gvalid) {
            int hidx2 = (gnext * NB + gn) * LHIST + gl;
            iu2 = hist_uv[hidx2]; ir2 = hist_r[hidx2];
        }

        __syncthreads();                               // S2: exps + o ready

        // ---- softmax weighted sum (no MUFU in the hot loop) ----
        {
            const float* eg = fLG + sn * LHIST;
            const __half* ob = hA0 + sn * LHIST * SH + sdo;
            float s = 0.f, acc = 0.f;
#pragma unroll 10
            for (int l = 0; l < LHIST; l++) {
                float e = eg[l];
                s += e;
                acc = fmaf(e, __half2float(ob[l * SH]), acc);
            }
            out[(size_t)(b0 + sn) * 64 + sd] = acc / s;
        }
        __syncthreads();                               // S3: A0/fLG/fUVA free

        iu = iu2; ir = ir2;
    }
}

extern "C" void kernel_launch(void* const* d_in, const int* in_sizes, int n_in,
                              void* d_out, int out_size) {
    const int*   nodes = (const int*)d_in[0];
    const int*   huv   = (const int*)d_in[1];
    const int*   hr    = (const int*)d_in[2];
    const float* v2e   = (const float*)d_in[3];
    const float* u2e   = (const float*)d_in[4];
    const float* r2e   = (const float*)d_in[5];
    const float* w1    = (const float*)d_in[6];
    const float* b1    = (const float*)d_in[7];
    const float* w2    = (const float*)d_in[8];
    const float* b2    = (const float*)d_in[9];
    const float* a1w   = (const float*)d_in[10];
    const float* a1b   = (const float*)d_in[11];
    const float* a2w   = (const float*)d_in[12];
    const float* a2b   = (const float*)d_in[13];
    const float* a3w   = (const float*)d_in[14];
    const float* a3b   = (const float*)d_in[15];
    float* out = (float*)d_out;

    const int B = in_sizes[0];
    const int ngroups = B / NB;
    const int nv = in_sizes[3] / 64;   // 100000
    const int nr = in_sizes[5] / 64;   // 5

    static int attr_set = 0;
    if (!attr_set) {
        cudaFuncSetAttribute(uv_agg_ra, cudaFuncAttributeMaxDynamicSharedMemorySize, SMEM_BYTES);
        attr_set = 1;
    }

    int tot = (nv + nr) * 32;
    convert_tables<<<(tot + 255) / 256, 256>>>(v2e, r2e, nv, nr);
    uv_agg_ra<<<444, TPB, SMEM_BYTES>>>(nodes, huv, hr, u2e,
                                        w1, b1, w2, b2, a1w, a1b, a2w, a2b,
                                        a3w, a3b, out, ngroups);
}